// round 17
// baseline (speedup 1.0000x reference)
#include <cuda_runtime.h>
#include <math.h>

#define NB 32
#define NT 1024
#define ND 512
#define NN 16
#define NDEPTH 3
#define NCHUNK 64
#define TC (NT / NCHUNK)   // 16 timesteps per partial-sum chunk
#define TTO 8              // timesteps per output block (threadIdx.y pair: 4 each)

// Scratch (static device globals — no allocation)
__device__ float g_partial[NB * NCHUNK * ND];      // 4 MB partial sums
__device__ float g_A[NDEPTH * NB * ND];            // per-depth additive offset c_d[b,:]
__device__ float g_S[NDEPTH * NB * ND];            // per-depth scale sel_d[b,:]
__device__ int   g_cnt[NB];                        // per-batch arrival counters (self-resetting)

// evict_last load of a float4 (keeps x biased to stay in L2 until out reads it)
__device__ __forceinline__ float4 ld_evict_last(const float4* p, unsigned long long pol) {
    float4 v;
    asm volatile("ld.global.L2::cache_hint.v4.f32 {%0,%1,%2,%3}, [%4], %5;"
                 : "=f"(v.x), "=f"(v.y), "=f"(v.z), "=f"(v.w)
                 : "l"(p), "l"(pol));
    return v;
}

// ---------------------------------------------------------------------------
// Kernel 1 (fused): pool partial sums + per-batch decide in the tail.
// grid = NB*NCHUNK = 2048 blocks, 128 threads.
// Pool phase identical to best-measured version. The 64th block to finish a
// batch (tracked by g_cnt[b]) runs the decision chain for that batch, fully
// overlapped with the remaining pool waves. Counters self-reset for graph
// replay. Arithmetic order is bitwise-identical to the standalone decide.
// ---------------------------------------------------------------------------
__global__ void __launch_bounds__(128) pool_decide_kernel(
    const float* __restrict__ x,
    const float* __restrict__ kd0, const float* __restrict__ kd1,
    const float* __restrict__ kd2,
    const float* __restrict__ vd0, const float* __restrict__ vd1,
    const float* __restrict__ vd2,
    const float* __restrict__ W,  const float* __restrict__ gum) {
    unsigned long long pol;
    asm volatile("createpolicy.fractional.L2::evict_last.b64 %0, 1.0;" : "=l"(pol));

    int blk = blockIdx.x;               // b * NCHUNK + chunk
    int b = blk >> 6;                   // / NCHUNK
    int c = blk & (NCHUNK - 1);
    int tid = threadIdx.x;              // 0..127

    {   // ---- pool phase ----
        const float4* xp = (const float4*)(x) + ((size_t)b * NT + (size_t)c * TC) * (ND / 4) + tid;
        float4 v[TC];
#pragma unroll
        for (int t = 0; t < TC; ++t)
            v[t] = ld_evict_last(xp + (size_t)t * (ND / 4), pol);
#pragma unroll
        for (int s = TC / 2; s > 0; s >>= 1)
#pragma unroll
            for (int t = 0; t < s; ++t) {
                v[t].x += v[t + s].x; v[t].y += v[t + s].y;
                v[t].z += v[t + s].z; v[t].w += v[t + s].w;
            }
        ((float4*)g_partial)[(size_t)blk * (ND / 4) + tid] = v[0];
    }

    // ---- arrival protocol ----
    __threadfence();                    // publish partials
    __syncthreads();
    __shared__ int sticket;
    if (tid == 0) sticket = atomicAdd(&g_cnt[b], 1);
    __syncthreads();
    if (sticket != NCHUNK - 1) return;  // not the last arrival for batch b
    __threadfence();                    // acquire all partials of batch b

    // ---- decide phase (128 threads, 4 dims per thread, 4 nodes per warp) ----
    int lane = tid & 31;
    int w = tid >> 5;                   // warp 0..3

    __shared__ float sp[ND];
    __shared__ float slog[NN];
    __shared__ int   sik;

    // pooled[b, i] for this thread's 4 dims (i = q*128 + tid), same sum order
    float pooled[4];
#pragma unroll
    for (int q = 0; q < 4; ++q) {
        int i = q * 128 + tid;
        float acc = 0.f;
#pragma unroll
        for (int c0 = 0; c0 < NCHUNK; c0 += 8) {
            float p[8];
#pragma unroll
            for (int j = 0; j < 8; ++j)
                p[j] = g_partial[(size_t)(b * NCHUNK + c0 + j) * ND + i];
#pragma unroll
            for (int j = 0; j < 8; ++j) acc += p[j];
        }
        pooled[q] = acc * (1.0f / NT);
    }

    const float* kds[NDEPTH] = {kd0, kd1, kd2};
    const float* vds[NDEPTH] = {vd0, vd1, vd2};

    float cacc[4] = {0.f, 0.f, 0.f, 0.f};
    int node = 0;
    int ik = 0;

    for (int d = 0; d < NDEPTH; ++d) {
        if (d > 0) {
#pragma unroll
            for (int q = 0; q < 4; ++q)
                cacc[q] += W[(size_t)ik * ND + q * 128 + tid];
        }
#pragma unroll
        for (int q = 0; q < 4; ++q)
            sp[q * 128 + tid] = pooled[q] + cacc[q];
        __syncthreads();

        // warp w computes logits for nodes 4w..4w+3 (same per-node order)
#pragma unroll
        for (int k = 0; k < 4; ++k) {
            int n = w * 4 + k;
            const float* krow = kds[d] + ((size_t)node * NN + n) * ND;
            float s = 0.f;
#pragma unroll
            for (int j = lane; j < ND; j += 32) s += sp[j] * krow[j];
#pragma unroll
            for (int o = 16; o; o >>= 1) s += __shfl_down_sync(0xffffffffu, s, o);
            if (lane == 0) slog[n] = s;
        }
        __syncthreads();

        // warp 0: argmax over (logits + gumbel), first-max wins
        if (w == 0) {
            float sc = (lane < NN)
                ? slog[lane] + gum[((size_t)d * NB + b) * NN + lane]
                : -INFINITY;
            int best = lane;
#pragma unroll
            for (int o = 8; o; o >>= 1) {
                float osc = __shfl_down_sync(0xffffffffu, sc, o);
                int obest = __shfl_down_sync(0xffffffffu, best, o);
                if (osc > sc) { sc = osc; best = obest; }
            }
            if (lane == 0) sik = best;
        }
        __syncthreads();
        ik = sik;

#pragma unroll
        for (int q = 0; q < 4; ++q) {
            int i = q * 128 + tid;
            g_A[((size_t)d * NB + b) * ND + i] = cacc[q];
            g_S[((size_t)d * NB + b) * ND + i] = vds[d][((size_t)node * NN + ik) * ND + i];
        }
        node = node * NN + ik;
    }

    if (tid == 0) g_cnt[b] = 0;         // reset for next graph replay
}

// ---------------------------------------------------------------------------
// Kernel 2: streaming output (best measured). Reverse-order over x (LIFO L2
// reuse of pool's tail), __ldcs reads, interleaved evict-first stores:
//   out[d,b,t,:] = (x[b,t,:] + A[d,b,:]) * S[d,b,:]
// grid = (NT/TTO = 128, NB), blockDim = (128, 2); 4 t's per thread.
// ---------------------------------------------------------------------------
__global__ void __launch_bounds__(256) out_kernel(const float* __restrict__ x,
                                                  float* __restrict__ out) {
    int b  = NB - 1 - blockIdx.y;                       // reversed batch
    int tb = (NT / TTO) - 1 - blockIdx.x;               // reversed t-block
    int g = threadIdx.x;                                // float4 dim group 0..127
    int t0 = tb * TTO + threadIdx.y * (TTO / 2);        // 4 consecutive t's

    const float4* A4 = (const float4*)g_A;
    const float4* S4 = (const float4*)g_S;
    int off = b * (ND / 4) + g;
    float4 a0 = A4[0 * NB * (ND / 4) + off];
    float4 a1 = A4[1 * NB * (ND / 4) + off];
    float4 a2 = A4[2 * NB * (ND / 4) + off];
    float4 s0 = S4[0 * NB * (ND / 4) + off];
    float4 s1 = S4[1 * NB * (ND / 4) + off];
    float4 s2 = S4[2 * NB * (ND / 4) + off];

    const float4* xp = (const float4*)x;
    float4* op = (float4*)out;
    const size_t stride_d = (size_t)NB * NT * (ND / 4);
    const size_t base = ((size_t)b * NT + t0) * (ND / 4) + g;

    float4 v[TTO / 2];
#pragma unroll
    for (int i = 0; i < TTO / 2; ++i)
        v[i] = __ldcs(&xp[base + (size_t)i * (ND / 4)]);

#pragma unroll
    for (int i = 0; i < TTO / 2; ++i) {
        size_t idx = base + (size_t)i * (ND / 4);
        float4 r0, r1, r2;
        r0.x = (v[i].x + a0.x) * s0.x; r0.y = (v[i].y + a0.y) * s0.y;
        r0.z = (v[i].z + a0.z) * s0.z; r0.w = (v[i].w + a0.w) * s0.w;
        r1.x = (v[i].x + a1.x) * s1.x; r1.y = (v[i].y + a1.y) * s1.y;
        r1.z = (v[i].z + a1.z) * s1.z; r1.w = (v[i].w + a1.w) * s1.w;
        r2.x = (v[i].x + a2.x) * s2.x; r2.y = (v[i].y + a2.y) * s2.y;
        r2.z = (v[i].z + a2.z) * s2.z; r2.w = (v[i].w + a2.w) * s2.w;
        __stcs(&op[idx], r0);
        __stcs(&op[idx + stride_d], r1);
        __stcs(&op[idx + 2 * stride_d], r2);
    }
}

// ---------------------------------------------------------------------------
extern "C" void kernel_launch(void* const* d_in, const int* in_sizes, int n_in,
                              void* d_out, int out_size) {
    const float* x   = (const float*)d_in[0];
    const float* kd0 = (const float*)d_in[1];
    const float* kd1 = (const float*)d_in[2];
    const float* kd2 = (const float*)d_in[3];
    const float* vd0 = (const float*)d_in[4];
    const float* vd1 = (const float*)d_in[5];
    const float* vd2 = (const float*)d_in[6];
    const float* W   = (const float*)d_in[7];
    const float* gum = (const float*)d_in[8];
    float* out = (float*)d_out;

    pool_decide_kernel<<<NB * NCHUNK, 128>>>(x, kd0, kd1, kd2, vd0, vd1, vd2, W, gum);
    out_kernel<<<dim3(NT / TTO, NB), dim3(128, 2)>>>(x, out);
}